// round 9
// baseline (speedup 1.0000x reference)
#include <cuda_runtime.h>
#include <math.h>

#define HH 240
#define WW 320
#define HWPIX (HH * WW)
#define NC 10
#define NCOL 8                           // columns per vote unit
#define NPAIR (NCOL / 2)                 // 4 column pairs (2 cols packed per word)
#define NGRP (WW / NCOL)                 // 40 column groups
#define NCTA (NC * NGRP)                 // 400 CTAs, one per (class, colgroup)
#define APB (HWPIX / NCTA)               // 192 pixels per CTA in phases A/C

// ---- packed f32x2 helpers (sm_103a) -----------------------------------------
#define PK2(out, lo, hi) \
    asm("mov.b64 %0, {%1, %2};" : "=l"(out) : "f"(lo), "f"(hi))
#define UPK2(lo, hi, in) \
    asm("mov.b64 {%0, %1}, %2;" : "=f"(lo), "=f"(hi) : "l"(in))
#define MUL2(out, a, b) \
    asm("mul.rn.f32x2 %0, %1, %2;" : "=l"(out) : "l"(a), "l"(b))
#define ADD2(out, a, b) \
    asm("add.rn.f32x2 %0, %1, %2;" : "=l"(out) : "l"(a), "l"(b))

// ---------------- scratch (static device globals; zero at load) --------------
// The last CTA re-zeroes everything consumed, so every launch (graph replays
// included) starts from zeroed scratch.
__device__ int                g_count[NC];
__device__ unsigned long long g_best[NC];
__device__ int                g_icnt[NC];
__device__ float              g_dsum[NC];
__device__ unsigned           g_done;
__device__ unsigned           g_bar1, g_bar2;
__device__ uint2              g_pix[NC][HWPIX];   // (x | y<<16), slope bits

// ---- device-wide barrier (grid co-resident: 400 CTAs, >=3/SM occupancy) -----
__device__ __forceinline__ void grid_barrier(unsigned* ctr) {
    __syncthreads();
    if (threadIdx.x == 0) {
        __threadfence();
        atomicAdd(ctr, 1u);
        while (*(volatile unsigned*)ctr < (unsigned)NCTA) __nanosleep(32);
        __threadfence();
    }
    __syncthreads();
}

// ---- branchless emit of one column pair into a 16+16-packed counter word ----
// even column = low 16 bits, odd column = high 16 bits. Per-half counts are
// bounded by the class pixel count (~7k) << 65536 -> halves never carry.
// Single predicated ATOMS per 'if' (no divergent branch region).
__device__ __forceinline__ void emit_pair(unsigned* wp, float fa, float fb) {
    const int  ra = __float2int_rn(fa);             // F2I.RND: round-half-even
    const int  rb = __float2int_rn(fb);
    const bool va = (unsigned)ra < (unsigned)HH;
    const bool vb = (unsigned)rb < (unsigned)HH;
    const bool mg = va && vb && (ra == rb);         // both votes -> one word
    const unsigned incA = mg ? 0x00010001u : 1u;
    if (va)        atomicAdd(&wp[ra], incA);
    if (vb && !mg) atomicAdd(&wp[rb], 0x00010000u);
}

// ---- vote for one pixel over an 8-column window ------------------------------
// yv_j = y + slope*(col_j - x), IEEE-rn packed == bit-identical to scalar.
__device__ __forceinline__ void vote_pixel(unsigned exy, unsigned sbits, int colbase,
                                           unsigned* hist,
                                           unsigned long long c22,
                                           unsigned long long c44,
                                           unsigned long long c66) {
    const int   xi = (int)(exy & 0xFFFFu);
    const float yf = (float)(exy >> 16);
    const float s  = __uint_as_float(sbits);

    unsigned long long s2, y2;
    PK2(s2, s, s);
    PK2(y2, yf, yf);

    const float d0 = (float)(colbase - xi);          // exact small integer
    unsigned long long dp01, dp67, m, y01, y67;
    PK2(dp01, d0, d0 + 1.0f);
    ADD2(dp67, dp01, c66);
    MUL2(m, s2, dp01); ADD2(y01, y2, m);
    MUL2(m, s2, dp67); ADD2(y67, y2, m);

    float f0, f1, f6, f7;
    UPK2(f0, f1, y01);
    UPK2(f6, f7, y67);

    // monotone in column -> endpoints bound the window
    const float mn = fminf(f0, f7), mx = fmaxf(f0, f7);
    if (mx < -0.5f || mn > 239.5f) return;

    unsigned long long dp23, dp45, y23, y45;
    ADD2(dp23, dp01, c22);
    ADD2(dp45, dp01, c44);
    MUL2(m, s2, dp23); ADD2(y23, y2, m);
    MUL2(m, s2, dp45); ADD2(y45, y2, m);
    float f2, f3, f4, f5;
    UPK2(f2, f3, y23);
    UPK2(f4, f5, y45);

    emit_pair(hist + 0 * HH, f0, f1);
    emit_pair(hist + 1 * HH, f2, f3);
    emit_pair(hist + 2 * HH, f4, f5);
    emit_pair(hist + 3 * HH, f6, f7);
}

// ---------------- fused persistent kernel -------------------------------------
__global__ __launch_bounds__(256, 3) void hough_fused(const int* __restrict__ label,
                                                      const float* __restrict__ cm,
                                                      float* __restrict__ out) {
    __shared__ unsigned           hist[NPAIR * HH];   // 3840 B (16+16 packed)
    __shared__ unsigned long long red[256];           // 2048 B
    __shared__ int   s_cnt[NC], s_base[NC];
    __shared__ int   scnt3[NC];
    __shared__ float ssum3[NC];
    __shared__ bool  s_last;

    const int bid  = blockIdx.x;      // 0..399
    const int t    = threadIdx.x;
    const int lane = t & 31;

    // ================= Phase A: compact masked pixels per class ==============
    if (t < NC) s_cnt[t] = 0;
    __syncthreads();

    int   c = -1, pos = 0;
    float slope = 0.0f, dirx = 0.0f, diry = 0.0f;
    const int p = bid * APB + t;                     // t<APB threads cover HWPIX
    if (t < APB) {
        const int lab = label[p];
        if (lab >= 1 && lab <= NC) c = lab - 1;
        const unsigned active = __ballot_sync(0xFFFFFFFFu, c >= 0);
        if (c >= 0) {
            const unsigned peers  = __match_any_sync(active, c);
            const int      leader = __ffs(peers) - 1;
            const int      rank   = __popc(peers & ((1u << lane) - 1u));
            int wbase = 0;
            if (lane == leader) wbase = atomicAdd(&s_cnt[c], __popc(peers));
            wbase = __shfl_sync(peers, wbase, leader);
            pos = wbase + rank;
            dirx  = cm[(3 * c + 0) * HWPIX + p];
            diry  = cm[(3 * c + 1) * HWPIX + p];
            slope = __fdiv_rn(diry, dirx);           // jnp c3[1]/c3[0]
        }
    }
    __syncthreads();
    if (t < NC && s_cnt[t] > 0) s_base[t] = atomicAdd(&g_count[t], s_cnt[t]);
    __syncthreads();
    if (c >= 0) {
        uint2 e;
        e.x = (unsigned)((p % WW) | ((p / WW) << 16));
        e.y = __float_as_uint(slope);
        g_pix[c][s_base[c] + pos] = e;
    }

    grid_barrier(&g_bar1);

    // ================= Phase B: Hough vote ====================================
    const int vc      = bid / NGRP;            // class
    const int colbase = (bid % NGRP) * NCOL;   // first column of window
    {
        for (int i = t; i < NPAIR * HH; i += 256) hist[i] = 0u;
        __syncthreads();

        unsigned long long c22, c44, c66;
        PK2(c22, 2.0f, 2.0f);
        PK2(c44, 4.0f, 4.0f);
        PK2(c66, 6.0f, 6.0f);

        const int n  = __ldcg(&g_count[vc]);
        const int n2 = n >> 1;
        const uint4* __restrict__ pix4 = (const uint4*)g_pix[vc];

        for (int i = t; i < n2; i += 256) {
            const uint4 e = pix4[i];
            vote_pixel(e.x, e.y, colbase, hist, c22, c44, c66);
            vote_pixel(e.z, e.w, colbase, hist, c22, c44, c66);
        }
        if ((n & 1) && t == 0) {
            const uint2 e = g_pix[vc][n - 1];
            vote_pixel(e.x, e.y, colbase, hist, c22, c44, c66);
        }
        __syncthreads();

        // block argmax: max count, tie -> lowest flat bin
        unsigned long long key = 0ULL;
        for (int i = t; i < NPAIR * HH; i += 256) {
            const int j2 = i / HH, row = i % HH;
            const unsigned w = hist[i];
            const unsigned binA = (unsigned)(row * WW + colbase + j2 * 2);
            const unsigned long long kA =
                ((unsigned long long)(w & 0xFFFFu) << 32) |
                (unsigned long long)(0xFFFFFFFFu - binA);
            const unsigned long long kB =
                ((unsigned long long)(w >> 16) << 32) |
                (unsigned long long)(0xFFFFFFFFu - (binA + 1));
            const unsigned long long k = kA > kB ? kA : kB;
            if (k > key) key = k;
        }
        red[t] = key;
        __syncthreads();
        #pragma unroll
        for (int s = 128; s > 0; s >>= 1) {
            if (t < s) { if (red[t + s] > red[t]) red[t] = red[t + s]; }
            __syncthreads();
        }
        if (t == 0) atomicMax(&g_best[vc], red[0]);
    }

    grid_barrier(&g_bar2);

    // ================= Phase C: inlier + depth + finalize =====================
    if (t < NC) { scnt3[t] = 0; ssum3[t] = 0.0f; }
    __syncthreads();

    if (c >= 0) {
        const unsigned long long best = __ldcg(&g_best[c]);
        const unsigned bin = 0xFFFFFFFFu - (unsigned)best;
        const float cx = (float)(bin % WW);
        const float cy = (float)(bin / WW);
        const float xf = (float)(p % WW), yf = (float)(p / WW);
        const float disx = xf - cx, disy = yf - cy;
        const float dn  = sqrtf(disx * disx + disy * disy);  // 0 -> NaN -> excluded
        const float dot = fabsf(disx / dn * dirx + disy / dn * diry);
        if (dot >= 0.9f) {
            atomicAdd(&scnt3[c], 1);
            atomicAdd(&ssum3[c], cm[(3 * c + 2) * HWPIX + p]);
        }
    }
    __syncthreads();

    if (t < NC && scnt3[t] > 0) {
        atomicAdd(&g_icnt[t], scnt3[t]);
        atomicAdd(&g_dsum[t], ssum3[t]);
    }
    __threadfence();
    if (t == 0) s_last = (atomicAdd(&g_done, 1u) == (unsigned)(NCTA - 1));
    __syncthreads();

    if (s_last) {
        __threadfence();
        if (t < NC) {
            const int cc = t;
            const unsigned long long best = __ldcg(&g_best[cc]);
            const unsigned cntBest = (unsigned)(best >> 32);
            const unsigned bin     = 0xFFFFFFFFu - (unsigned)best;
            const float cx = (float)(bin % WW);
            const float cy = (float)(bin / WW);
            const bool trig = (__ldcg(&g_count[cc]) >= 500) && (cntBest > 500u);
            const int   icnt = __ldcg(&g_icnt[cc]);
            const float dsum = __ldcg(&g_dsum[cc]);
            const float dmean = (icnt > 0) ? (dsum / (float)icnt)
                                           : __int_as_float(0x7fc00000);
            out[cc * 2 + 0]  = trig ? cx    : 0.0f;   // centers (1,10,2)
            out[cc * 2 + 1]  = trig ? cy    : 0.0f;
            out[2 * NC + cc] = trig ? dmean : 0.0f;   // depths (1,10)
            g_icnt[cc]  = 0;
            g_dsum[cc]  = 0.0f;
            g_count[cc] = 0;
            g_best[cc]  = 0ULL;
        }
        if (t == 0) { g_done = 0u; g_bar1 = 0u; g_bar2 = 0u; }
    }
}

// ---------------- launch ------------------------------------------------------
extern "C" void kernel_launch(void* const* d_in, const int* in_sizes, int n_in,
                              void* d_out, int out_size) {
    const int*   label;
    const float* cm;
    if (in_sizes[0] == HWPIX) {
        label = (const int*)d_in[0];
        cm    = (const float*)d_in[1];
    } else {
        label = (const int*)d_in[1];
        cm    = (const float*)d_in[0];
    }
    hough_fused<<<NCTA, 256>>>(label, cm, (float*)d_out);
}

// round 10
// speedup vs baseline: 1.1306x; 1.1306x over previous
#include <cuda_runtime.h>
#include <math.h>

#define HH 240
#define WW 320
#define HWPIX (HH * WW)
#define NC 10
#define NCOL 8                           // columns per vote unit
#define NGRP (WW / NCOL)                 // 40 column groups
#define NCTA (NC * NGRP)                 // 400 CTAs, one per (class, colgroup)
#define APB (HWPIX / NCTA)               // 192 pixels per CTA in phases A/C

// ---- packed f32x2 helpers (sm_103a) -----------------------------------------
#define PK2(out, lo, hi) \
    asm("mov.b64 %0, {%1, %2};" : "=l"(out) : "f"(lo), "f"(hi))
#define UPK2(lo, hi, in) \
    asm("mov.b64 {%0, %1}, %2;" : "=f"(lo), "=f"(hi) : "l"(in))
#define MUL2(out, a, b) \
    asm("mul.rn.f32x2 %0, %1, %2;" : "=l"(out) : "l"(a), "l"(b))
#define ADD2(out, a, b) \
    asm("add.rn.f32x2 %0, %1, %2;" : "=l"(out) : "l"(a), "l"(b))

// ---------------- scratch (static device globals; zero at load) --------------
// The last CTA re-zeroes everything consumed, so every launch (graph replays
// included) starts from zeroed scratch.
__device__ int                g_count[NC];
__device__ unsigned long long g_best[NC];
__device__ int                g_icnt[NC];
__device__ float              g_dsum[NC];
__device__ unsigned           g_done;
__device__ unsigned           g_bar1, g_bar2;
__device__ __align__(16) uint2 g_pix[NC][HWPIX];  // (x | y<<16), slope bits

// ---- device-wide barrier (grid co-resident: 400 CTAs, >=3/SM occupancy) -----
__device__ __forceinline__ void grid_barrier(unsigned* ctr) {
    __syncthreads();
    if (threadIdx.x == 0) {
        __threadfence();
        atomicAdd(ctr, 1u);
        while (*(volatile unsigned*)ctr < (unsigned)NCTA) __nanosleep(32);
        __threadfence();
    }
    __syncthreads();
}

// ---- vote for one pixel over an 8-column window ------------------------------
// yv_j = y + slope*(col_j - x), IEEE-rn packed == bit-identical to scalar.
__device__ __forceinline__ void vote_pixel(unsigned exy, unsigned sbits, int colbase,
                                           unsigned* hist,
                                           unsigned long long c22,
                                           unsigned long long c44,
                                           unsigned long long c66) {
    const int   xi = (int)(exy & 0xFFFFu);
    const float yf = (float)(exy >> 16);
    const float s  = __uint_as_float(sbits);

    unsigned long long s2, y2;
    PK2(s2, s, s);
    PK2(y2, yf, yf);

    const float d0 = (float)(colbase - xi);          // exact small integer
    unsigned long long dp01, dp67, m, y01, y67;
    PK2(dp01, d0, d0 + 1.0f);
    ADD2(dp67, dp01, c66);
    MUL2(m, s2, dp01); ADD2(y01, y2, m);
    MUL2(m, s2, dp67); ADD2(y67, y2, m);

    float f0, f1, f6, f7;
    UPK2(f0, f1, y01);
    UPK2(f6, f7, y67);

    // monotone in column -> endpoints bound the window
    const float mn = fminf(f0, f7), mx = fmaxf(f0, f7);
    if (mx < -0.5f || mn > 239.5f) return;

    unsigned long long dp23, dp45, y23, y45;
    ADD2(dp23, dp01, c22);
    ADD2(dp45, dp01, c44);
    MUL2(m, s2, dp23); ADD2(y23, y2, m);
    MUL2(m, s2, dp45); ADD2(y45, y2, m);
    float f2, f3, f4, f5;
    UPK2(f2, f3, y23);
    UPK2(f4, f5, y45);

    int r;
    r = __float2int_rn(f0); if ((unsigned)r < (unsigned)HH) atomicAdd(&hist[0 * HH + r], 1u);
    r = __float2int_rn(f1); if ((unsigned)r < (unsigned)HH) atomicAdd(&hist[1 * HH + r], 1u);
    r = __float2int_rn(f2); if ((unsigned)r < (unsigned)HH) atomicAdd(&hist[2 * HH + r], 1u);
    r = __float2int_rn(f3); if ((unsigned)r < (unsigned)HH) atomicAdd(&hist[3 * HH + r], 1u);
    r = __float2int_rn(f4); if ((unsigned)r < (unsigned)HH) atomicAdd(&hist[4 * HH + r], 1u);
    r = __float2int_rn(f5); if ((unsigned)r < (unsigned)HH) atomicAdd(&hist[5 * HH + r], 1u);
    r = __float2int_rn(f6); if ((unsigned)r < (unsigned)HH) atomicAdd(&hist[6 * HH + r], 1u);
    r = __float2int_rn(f7); if ((unsigned)r < (unsigned)HH) atomicAdd(&hist[7 * HH + r], 1u);
}

// ---------------- fused persistent kernel -------------------------------------
__global__ __launch_bounds__(256, 3) void hough_fused(const int* __restrict__ label,
                                                      const float* __restrict__ cm,
                                                      float* __restrict__ out) {
    __shared__ unsigned           hist[NCOL * HH];    // 7680 B
    __shared__ unsigned long long red[256];           // 2048 B
    __shared__ int   s_cnt[NC], s_base[NC];
    __shared__ int   scnt3[NC];
    __shared__ float ssum3[NC];
    __shared__ bool  s_last;

    const int bid  = blockIdx.x;      // 0..399
    const int t    = threadIdx.x;
    const int lane = t & 31;
    const int warp = t >> 5;

    // ================= Phase A: compact masked pixels per class ==============
    if (t < NC) s_cnt[t] = 0;
    __syncthreads();

    int   c = -1, pos = 0;
    float slope = 0.0f, dirx = 0.0f, diry = 0.0f;
    const int p = bid * APB + t;                     // t<APB threads cover HWPIX
    if (t < APB) {
        const int lab = label[p];
        if (lab >= 1 && lab <= NC) c = lab - 1;
        const unsigned active = __ballot_sync(0xFFFFFFFFu, c >= 0);
        if (c >= 0) {
            const unsigned peers  = __match_any_sync(active, c);
            const int      leader = __ffs(peers) - 1;
            const int      rank   = __popc(peers & ((1u << lane) - 1u));
            int wbase = 0;
            if (lane == leader) wbase = atomicAdd(&s_cnt[c], __popc(peers));
            wbase = __shfl_sync(peers, wbase, leader);
            pos = wbase + rank;
            dirx  = cm[(3 * c + 0) * HWPIX + p];
            diry  = cm[(3 * c + 1) * HWPIX + p];
            slope = __fdiv_rn(diry, dirx);           // jnp c3[1]/c3[0]
        }
    }
    __syncthreads();
    if (t < NC && s_cnt[t] > 0) s_base[t] = atomicAdd(&g_count[t], s_cnt[t]);
    __syncthreads();
    if (c >= 0) {
        uint2 e;
        e.x = (unsigned)((p % WW) | ((p / WW) << 16));
        e.y = __float_as_uint(slope);
        g_pix[c][s_base[c] + pos] = e;
    }

    grid_barrier(&g_bar1);

    // ================= Phase B: Hough vote ====================================
    const int vc      = bid / NGRP;            // class
    const int colbase = (bid % NGRP) * NCOL;   // first column of window
    {
        for (int i = t; i < NCOL * HH; i += 256) hist[i] = 0u;
        __syncthreads();

        unsigned long long c22, c44, c66;
        PK2(c22, 2.0f, 2.0f);
        PK2(c44, 4.0f, 4.0f);
        PK2(c66, 6.0f, 6.0f);

        const int n = __ldcg(&g_count[vc]);
        const uint4* __restrict__ pix4 = (const uint4*)g_pix[vc];

        // Lane-decorrelated visit order: each warp owns 256-pixel chunks;
        // lane l takes the 8 consecutive pixels [l*8, l*8+8) of the chunk.
        // Lanes are 8 pixels apart -> rows spread across bins -> no
        // same-address ATOMS pileup from spatially-coherent pixels.
        const int nch = (n + 255) >> 8;            // chunks of 256 pixels
        for (int ch = warp; ch < nch; ch += 8) {
            const int base4 = ch * 128 + lane * 4; // uint4 index (2 pixels each)
            #pragma unroll
            for (int g = 0; g < 4; ++g) {
                const int pos4 = base4 + g;
                const int p0   = pos4 * 2;
                const uint4 e  = pix4[pos4];
                if (p0 < n)     vote_pixel(e.x, e.y, colbase, hist, c22, c44, c66);
                if (p0 + 1 < n) vote_pixel(e.z, e.w, colbase, hist, c22, c44, c66);
            }
        }
        __syncthreads();

        // block argmax: max count, tie -> lowest flat bin
        unsigned long long key = 0ULL;
        #pragma unroll
        for (int j = 0; j < NCOL; ++j) {
            if (t < HH) {
                const unsigned bin = (unsigned)(t * WW + colbase + j);
                const unsigned long long k =
                    ((unsigned long long)hist[j * HH + t] << 32) |
                    (unsigned long long)(0xFFFFFFFFu - bin);
                if (k > key) key = k;
            }
        }
        red[t] = key;
        __syncthreads();
        #pragma unroll
        for (int s = 128; s > 0; s >>= 1) {
            if (t < s) { if (red[t + s] > red[t]) red[t] = red[t + s]; }
            __syncthreads();
        }
        if (t == 0) atomicMax(&g_best[vc], red[0]);
    }

    grid_barrier(&g_bar2);

    // ================= Phase C: inlier + depth + finalize =====================
    if (t < NC) { scnt3[t] = 0; ssum3[t] = 0.0f; }
    __syncthreads();

    if (c >= 0) {
        const unsigned long long best = __ldcg(&g_best[c]);
        const unsigned bin = 0xFFFFFFFFu - (unsigned)best;
        const float cx = (float)(bin % WW);
        const float cy = (float)(bin / WW);
        const float xf = (float)(p % WW), yf = (float)(p / WW);
        const float disx = xf - cx, disy = yf - cy;
        const float dn  = sqrtf(disx * disx + disy * disy);  // 0 -> NaN -> excluded
        const float dot = fabsf(disx / dn * dirx + disy / dn * diry);
        if (dot >= 0.9f) {
            atomicAdd(&scnt3[c], 1);
            atomicAdd(&ssum3[c], cm[(3 * c + 2) * HWPIX + p]);
        }
    }
    __syncthreads();

    if (t < NC && scnt3[t] > 0) {
        atomicAdd(&g_icnt[t], scnt3[t]);
        atomicAdd(&g_dsum[t], ssum3[t]);
    }
    __threadfence();
    if (t == 0) s_last = (atomicAdd(&g_done, 1u) == (unsigned)(NCTA - 1));
    __syncthreads();

    if (s_last) {
        __threadfence();
        if (t < NC) {
            const int cc = t;
            const unsigned long long best = __ldcg(&g_best[cc]);
            const unsigned cntBest = (unsigned)(best >> 32);
            const unsigned bin     = 0xFFFFFFFFu - (unsigned)best;
            const float cx = (float)(bin % WW);
            const float cy = (float)(bin / WW);
            const bool trig = (__ldcg(&g_count[cc]) >= 500) && (cntBest > 500u);
            const int   icnt = __ldcg(&g_icnt[cc]);
            const float dsum = __ldcg(&g_dsum[cc]);
            const float dmean = (icnt > 0) ? (dsum / (float)icnt)
                                           : __int_as_float(0x7fc00000);
            out[cc * 2 + 0]  = trig ? cx    : 0.0f;   // centers (1,10,2)
            out[cc * 2 + 1]  = trig ? cy    : 0.0f;
            out[2 * NC + cc] = trig ? dmean : 0.0f;   // depths (1,10)
            g_icnt[cc]  = 0;
            g_dsum[cc]  = 0.0f;
            g_count[cc] = 0;
            g_best[cc]  = 0ULL;
        }
        if (t == 0) { g_done = 0u; g_bar1 = 0u; g_bar2 = 0u; }
    }
}

// ---------------- launch ------------------------------------------------------
extern "C" void kernel_launch(void* const* d_in, const int* in_sizes, int n_in,
                              void* d_out, int out_size) {
    const int*   label;
    const float* cm;
    if (in_sizes[0] == HWPIX) {
        label = (const int*)d_in[0];
        cm    = (const float*)d_in[1];
    } else {
        label = (const int*)d_in[1];
        cm    = (const float*)d_in[0];
    }
    hough_fused<<<NCTA, 256>>>(label, cm, (float*)d_out);
}

// round 11
// speedup vs baseline: 1.2267x; 1.0850x over previous
#include <cuda_runtime.h>
#include <math.h>

#define HH 240
#define WW 320
#define HWPIX (HH * WW)
#define NC 10
#define NCOL 8                           // columns per vote unit
#define NGRP (WW / NCOL)                 // 40 column groups
#define NCTA (NC * NGRP)                 // 400 CTAs, one per (class, colgroup)
#define NPIXBLK 300                      // 300 * 256 == 76800 == HWPIX

// ---- packed f32x2 helpers (sm_103a) -----------------------------------------
#define PK2(out, lo, hi) \
    asm("mov.b64 %0, {%1, %2};" : "=l"(out) : "f"(lo), "f"(hi))
#define UPK2(lo, hi, in) \
    asm("mov.b64 {%0, %1}, %2;" : "=f"(lo), "=f"(hi) : "l"(in))
#define MUL2(out, a, b) \
    asm("mul.rn.f32x2 %0, %1, %2;" : "=l"(out) : "l"(a), "l"(b))
#define ADD2(out, a, b) \
    asm("add.rn.f32x2 %0, %1, %2;" : "=l"(out) : "l"(a), "l"(b))

// ---------------- scratch (static device globals; zero at load) --------------
// The last CTA re-zeroes everything consumed, so every launch (graph replays
// included) starts from zeroed scratch.
__device__ int                g_count[NC];
__device__ unsigned long long g_best[NC];
__device__ int                g_icnt[NC];
__device__ float              g_dsum[NC];
__device__ unsigned           g_done;
__device__ unsigned           g_bar1, g_bar2;
__device__ __align__(16) uint2 g_pix[NC][HWPIX];  // (x | y<<16), slope bits

// ---- device-wide barrier (grid co-resident: 400 CTAs, >=3/SM occupancy) -----
__device__ __forceinline__ void grid_barrier(unsigned* ctr) {
    __syncthreads();
    if (threadIdx.x == 0) {
        __threadfence();
        atomicAdd(ctr, 1u);
        while (*(volatile unsigned*)ctr < (unsigned)NCTA) __nanosleep(32);
        __threadfence();
    }
    __syncthreads();
}

// ---- vote for one pixel over an 8-column window ------------------------------
// yv_j = y + slope*(col_j - x), IEEE-rn packed == bit-identical to scalar.
__device__ __forceinline__ void vote_pixel(unsigned exy, unsigned sbits, int colbase,
                                           unsigned* hist,
                                           unsigned long long c22,
                                           unsigned long long c44,
                                           unsigned long long c66) {
    const int   xi = (int)(exy & 0xFFFFu);
    const float yf = (float)(exy >> 16);
    const float s  = __uint_as_float(sbits);

    unsigned long long s2, y2;
    PK2(s2, s, s);
    PK2(y2, yf, yf);

    const float d0 = (float)(colbase - xi);          // exact small integer
    unsigned long long dp01, dp67, m, y01, y67;
    PK2(dp01, d0, d0 + 1.0f);
    ADD2(dp67, dp01, c66);
    MUL2(m, s2, dp01); ADD2(y01, y2, m);
    MUL2(m, s2, dp67); ADD2(y67, y2, m);

    float f0, f1, f6, f7;
    UPK2(f0, f1, y01);
    UPK2(f6, f7, y67);

    // monotone in column -> endpoints bound the window
    const float mn = fminf(f0, f7), mx = fmaxf(f0, f7);
    if (mx < -0.5f || mn > 239.5f) return;

    unsigned long long dp23, dp45, y23, y45;
    ADD2(dp23, dp01, c22);
    ADD2(dp45, dp01, c44);
    MUL2(m, s2, dp23); ADD2(y23, y2, m);
    MUL2(m, s2, dp45); ADD2(y45, y2, m);
    float f2, f3, f4, f5;
    UPK2(f2, f3, y23);
    UPK2(f4, f5, y45);

    int r;
    r = __float2int_rn(f0); if ((unsigned)r < (unsigned)HH) atomicAdd(&hist[0 * HH + r], 1u);
    r = __float2int_rn(f1); if ((unsigned)r < (unsigned)HH) atomicAdd(&hist[1 * HH + r], 1u);
    r = __float2int_rn(f2); if ((unsigned)r < (unsigned)HH) atomicAdd(&hist[2 * HH + r], 1u);
    r = __float2int_rn(f3); if ((unsigned)r < (unsigned)HH) atomicAdd(&hist[3 * HH + r], 1u);
    r = __float2int_rn(f4); if ((unsigned)r < (unsigned)HH) atomicAdd(&hist[4 * HH + r], 1u);
    r = __float2int_rn(f5); if ((unsigned)r < (unsigned)HH) atomicAdd(&hist[5 * HH + r], 1u);
    r = __float2int_rn(f6); if ((unsigned)r < (unsigned)HH) atomicAdd(&hist[6 * HH + r], 1u);
    r = __float2int_rn(f7); if ((unsigned)r < (unsigned)HH) atomicAdd(&hist[7 * HH + r], 1u);
}

// ---------------- fused persistent kernel -------------------------------------
__global__ __launch_bounds__(256, 3) void hough_fused(const int* __restrict__ label,
                                                      const float* __restrict__ cm,
                                                      float* __restrict__ out) {
    __shared__ unsigned           hist[NCOL * HH];    // 7680 B
    __shared__ unsigned long long red[256];           // 2048 B
    __shared__ int   s_cnt[NC], s_base[NC];
    __shared__ int   scnt3[NC];
    __shared__ float ssum3[NC];
    __shared__ bool  s_last;

    const int bid  = blockIdx.x;      // 0..399
    const int t    = threadIdx.x;
    const int lane = t & 31;

    // ================= Phase A: compact masked pixels per class ==============
    // Bit-reversed pixel assignment: thread t handles pixel bid*256+bitrev8(t).
    // Appended class-list runs are therefore bit-reversed image order, so when
    // phase B reads the list coalesced, its 32 lanes hold pixels >=8 apart ->
    // no same-bin (same smem address) ATOMS pileup from spatial coherence.
    if (t < NC) s_cnt[t] = 0;
    __syncthreads();

    int   c = -1, pos = 0;
    float slope = 0.0f, dirx = 0.0f, diry = 0.0f;
    const int t8 = (int)(__brev((unsigned)t) >> 24);   // bitrev8, t in [0,256)
    const int p  = bid * 256 + t8;
    if (bid < NPIXBLK) {
        const int lab = label[p];
        if (lab >= 1 && lab <= NC) c = lab - 1;
        const unsigned active = __ballot_sync(0xFFFFFFFFu, c >= 0);
        if (c >= 0) {
            const unsigned peers  = __match_any_sync(active, c);
            const int      leader = __ffs(peers) - 1;
            const int      rank   = __popc(peers & ((1u << lane) - 1u));
            int wbase = 0;
            if (lane == leader) wbase = atomicAdd(&s_cnt[c], __popc(peers));
            wbase = __shfl_sync(peers, wbase, leader);
            pos = wbase + rank;
            dirx  = cm[(3 * c + 0) * HWPIX + p];
            diry  = cm[(3 * c + 1) * HWPIX + p];
            slope = __fdiv_rn(diry, dirx);           // jnp c3[1]/c3[0]
        }
    }
    __syncthreads();
    if (t < NC && s_cnt[t] > 0) s_base[t] = atomicAdd(&g_count[t], s_cnt[t]);
    __syncthreads();
    if (c >= 0) {
        uint2 e;
        e.x = (unsigned)((p % WW) | ((p / WW) << 16));
        e.y = __float_as_uint(slope);
        g_pix[c][s_base[c] + pos] = e;
    }

    grid_barrier(&g_bar1);

    // ================= Phase B: Hough vote ====================================
    const int vc      = bid / NGRP;            // class
    const int colbase = (bid % NGRP) * NCOL;   // first column of window
    {
        for (int i = t; i < NCOL * HH; i += 256) hist[i] = 0u;
        __syncthreads();

        unsigned long long c22, c44, c66;
        PK2(c22, 2.0f, 2.0f);
        PK2(c44, 4.0f, 4.0f);
        PK2(c66, 6.0f, 6.0f);

        const int n  = __ldcg(&g_count[vc]);
        const int n2 = n >> 1;
        const uint4* __restrict__ pix4 = (const uint4*)g_pix[vc];

        for (int i = t; i < n2; i += 256) {          // fully coalesced
            const uint4 e = pix4[i];
            vote_pixel(e.x, e.y, colbase, hist, c22, c44, c66);
            vote_pixel(e.z, e.w, colbase, hist, c22, c44, c66);
        }
        if ((n & 1) && t == 0) {
            const uint2 e = g_pix[vc][n - 1];
            vote_pixel(e.x, e.y, colbase, hist, c22, c44, c66);
        }
        __syncthreads();

        // block argmax: max count, tie -> lowest flat bin
        unsigned long long key = 0ULL;
        for (int i = t; i < NCOL * HH; i += 256) {
            const int j = i / HH, row = i % HH;
            const unsigned bin = (unsigned)(row * WW + colbase + j);
            const unsigned long long k =
                ((unsigned long long)hist[i] << 32) |
                (unsigned long long)(0xFFFFFFFFu - bin);
            if (k > key) key = k;
        }
        red[t] = key;
        __syncthreads();
        #pragma unroll
        for (int s = 128; s > 0; s >>= 1) {
            if (t < s) { if (red[t + s] > red[t]) red[t] = red[t + s]; }
            __syncthreads();
        }
        if (t == 0) atomicMax(&g_best[vc], red[0]);
    }

    grid_barrier(&g_bar2);

    // ================= Phase C: inlier + depth + finalize =====================
    if (t < NC) { scnt3[t] = 0; ssum3[t] = 0.0f; }
    __syncthreads();

    if (c >= 0) {
        const unsigned long long best = __ldcg(&g_best[c]);
        const unsigned bin = 0xFFFFFFFFu - (unsigned)best;
        const float cx = (float)(bin % WW);
        const float cy = (float)(bin / WW);
        const float xf = (float)(p % WW), yf = (float)(p / WW);
        const float disx = xf - cx, disy = yf - cy;
        const float dn  = sqrtf(disx * disx + disy * disy);  // 0 -> NaN -> excluded
        const float dot = fabsf(disx / dn * dirx + disy / dn * diry);
        if (dot >= 0.9f) {
            atomicAdd(&scnt3[c], 1);
            atomicAdd(&ssum3[c], cm[(3 * c + 2) * HWPIX + p]);
        }
    }
    __syncthreads();

    if (t < NC && scnt3[t] > 0) {
        atomicAdd(&g_icnt[t], scnt3[t]);
        atomicAdd(&g_dsum[t], ssum3[t]);
    }
    __threadfence();
    if (t == 0) s_last = (atomicAdd(&g_done, 1u) == (unsigned)(NCTA - 1));
    __syncthreads();

    if (s_last) {
        __threadfence();
        if (t < NC) {
            const int cc = t;
            const unsigned long long best = __ldcg(&g_best[cc]);
            const unsigned cntBest = (unsigned)(best >> 32);
            const unsigned bin     = 0xFFFFFFFFu - (unsigned)best;
            const float cx = (float)(bin % WW);
            const float cy = (float)(bin / WW);
            const bool trig = (__ldcg(&g_count[cc]) >= 500) && (cntBest > 500u);
            const int   icnt = __ldcg(&g_icnt[cc]);
            const float dsum = __ldcg(&g_dsum[cc]);
            const float dmean = (icnt > 0) ? (dsum / (float)icnt)
                                           : __int_as_float(0x7fc00000);
            out[cc * 2 + 0]  = trig ? cx    : 0.0f;   // centers (1,10,2)
            out[cc * 2 + 1]  = trig ? cy    : 0.0f;
            out[2 * NC + cc] = trig ? dmean : 0.0f;   // depths (1,10)
            g_icnt[cc]  = 0;
            g_dsum[cc]  = 0.0f;
            g_count[cc] = 0;
            g_best[cc]  = 0ULL;
        }
        if (t == 0) { g_done = 0u; g_bar1 = 0u; g_bar2 = 0u; }
    }
}

// ---------------- launch ------------------------------------------------------
extern "C" void kernel_launch(void* const* d_in, const int* in_sizes, int n_in,
                              void* d_out, int out_size) {
    const int*   label;
    const float* cm;
    if (in_sizes[0] == HWPIX) {
        label = (const int*)d_in[0];
        cm    = (const float*)d_in[1];
    } else {
        label = (const int*)d_in[1];
        cm    = (const float*)d_in[0];
    }
    hough_fused<<<NCTA, 256>>>(label, cm, (float*)d_out);
}